// round 11
// baseline (speedup 1.0000x reference)
#include <cuda_runtime.h>
#include <cuda_fp16.h>
#include <cstdint>

// ============ helpers ============

__device__ __forceinline__ uint32_t smem_u32(const void* p) {
    uint32_t a;
    asm("{ .reg .u64 t; cvta.to.shared.u64 t, %1; cvt.u32.u64 %0, t; }" : "=r"(a) : "l"(p));
    return a;
}

__device__ __forceinline__ void cp_async16(uint32_t saddr, const void* gaddr) {
    asm volatile("cp.async.cg.shared.global [%0], [%1], 16;" :: "r"(saddr), "l"(gaddr));
}
#define CP_COMMIT() asm volatile("cp.async.commit_group;" ::: "memory")
#define CP_WAIT(N)  asm volatile("cp.async.wait_group %0;" :: "n"(N) : "memory")

__device__ __forceinline__ void ldsm_x4(uint32_t addr, uint32_t& r0, uint32_t& r1,
                                        uint32_t& r2, uint32_t& r3) {
    asm volatile("ldmatrix.sync.aligned.m8n8.x4.shared.b16 {%0,%1,%2,%3}, [%4];"
                 : "=r"(r0), "=r"(r1), "=r"(r2), "=r"(r3) : "r"(addr));
}

__device__ __forceinline__ void sts128(uint32_t a, uint32_t x, uint32_t y, uint32_t z, uint32_t w) {
    asm volatile("st.shared.v4.b32 [%0], {%1,%2,%3,%4};"
                 :: "r"(a), "r"(x), "r"(y), "r"(z), "r"(w) : "memory");
}

__device__ __forceinline__ void mma16816(float* c, const uint32_t* a, uint32_t b0, uint32_t b1) {
    asm volatile(
        "mma.sync.aligned.m16n8k16.row.col.f32.f16.f16.f32 "
        "{%0,%1,%2,%3}, {%4,%5,%6,%7}, {%8,%9}, {%0,%1,%2,%3};"
        : "+f"(c[0]), "+f"(c[1]), "+f"(c[2]), "+f"(c[3])
        : "r"(a[0]), "r"(a[1]), "r"(a[2]), "r"(a[3]), "r"(b0), "r"(b1));
}

__device__ __forceinline__ void split2(float v0, float v1, uint32_t& hi, uint32_t& lo) {
    __half h0 = __float2half_rn(v0), h1 = __float2half_rn(v1);
    __half2 hh = __halves2half2(h0, h1);
    hi = *(uint32_t*)&hh;
    __half2 ll = __floats2half2_rn(v0 - __half2float(h0), v1 - __half2float(h1));
    lo = *(uint32_t*)&ll;
}

// ============ device scratch ============

static constexpr size_t NEL = 16ull * 1024 * 1024;  // 16 x 1024 x 1024

__device__ __half g_w[NEL];     // softmax weights, fp16
__device__ __half g_et[NEL];    // E^T per batch, fp16: [b][d][k]
__device__ float  g_scores[NEL];

// ---- GEMM1 smem layout (k-chunk 16, LDG-direct convert, double-buffered tiles) ----
static constexpr int G1_TROW = 48;                   // 16 halves = 32B data + 16 pad (16B-aligned)
static constexpr int G1_TSZ  = 128 * G1_TROW;        // 6144 per tile
// per stage: QH, QL, EH, EL
static constexpr int G1_STAGE = 4 * G1_TSZ;          // 24576
static constexpr int G1_SMEM  = 2 * G1_STAGE;        // 49152

// ---- GEMM2 smem layout (k64, 3-slot rotation; R10-proven) ----
static constexpr int G2_ROW  = 144;                  // 64 halves = 128B data + 16 pad
static constexpr int G2_TILE = 128 * G2_ROW;         // 18432 B per operand
static constexpr int G2_SMEM = 3 * 2 * G2_TILE;      // 110592 B

// ============ E transpose-convert: fp32 [b][k][d] -> fp16 g_et [b][d][k] ============

__global__ void __launch_bounds__(256)
et_kernel(const float* __restrict__ enc) {
    __shared__ __half ts[64][65];
    int b = blockIdx.z;
    int d0 = blockIdx.x << 6, k0 = blockIdx.y << 6;
    size_t boff = (size_t)b << 20;
    int tid = threadIdx.x;
    int f4id = tid & 15, rr = tid >> 4;

    #pragma unroll
    for (int pass = 0; pass < 4; pass++) {
        int k = pass * 16 + rr;
        size_t go = boff + (size_t)(k0 + k) * 1024 + d0 + f4id * 4;
        float4 v = *(const float4*)(enc + go);
        int dc = f4id * 4;
        ts[k][dc]     = __float2half_rn(v.x);
        ts[k][dc + 1] = __float2half_rn(v.y);
        ts[k][dc + 2] = __float2half_rn(v.z);
        ts[k][dc + 3] = __float2half_rn(v.w);
    }
    __syncthreads();
    int lane = tid & 31;
    #pragma unroll
    for (int pass = 0; pass < 8; pass++) {
        int dd = pass * 8 + (tid >> 5);
        int kk = lane * 2;
        __half2 o = __halves2half2(ts[kk][dd], ts[kk + 1][dd]);
        *(__half2*)(g_et + boff + (size_t)(d0 + dd) * 1024 + k0 + kk) = o;
    }
}

// ============ GEMM1: scores = Q @ E^T, LDG-direct convert, 3-term split ============
// CTA 128x128, 8 warps (2M x 4N), k-chunk 16 (64 chunks), 1 sync/chunk, 2 CTAs/SM.

__global__ void __launch_bounds__(256, 2)
gemm1_kernel(const float* __restrict__ Q, const float* __restrict__ E) {
    extern __shared__ char smem[];
    uint32_t sb = smem_u32(smem);
    int tid = threadIdx.x, wid = tid >> 5, lane = tid & 31;
    int wm = wid >> 2, wn = wid & 3;
    int b = blockIdx.z;
    int m0 = blockIdx.y << 7, n0 = blockIdx.x << 7;
    size_t boff = (size_t)b << 20;

    // per-thread load/convert mapping: row = tid>>1, k-half = (tid&1)*8
    int crow = tid >> 1;
    int chalf = tid & 1;
    const float* gQ = Q + boff + (size_t)(m0 + crow) * 1024 + chalf * 8;
    const float* gE = E + boff + (size_t)(n0 + crow) * 1024 + chalf * 8;
    uint32_t cdst = crow * G1_TROW + chalf * 16;

    float c[4][4][4];
    #pragma unroll
    for (int i = 0; i < 4; i++)
        #pragma unroll
        for (int j = 0; j < 4; j++)
            #pragma unroll
            for (int k = 0; k < 4; k++) c[i][j][k] = 0.f;

    float4 qa0, qa1, ea0, ea1;  // held f32 chunk data (16 regs)

    // prologue: chunk0 -> regs -> T[0]; chunk1 -> regs
    {
        qa0 = *(const float4*)(gQ);     qa1 = *(const float4*)(gQ + 4);
        ea0 = *(const float4*)(gE);     ea1 = *(const float4*)(gE + 4);
        uint32_t hi[4], lo[4];
        split2(qa0.x, qa0.y, hi[0], lo[0]); split2(qa0.z, qa0.w, hi[1], lo[1]);
        split2(qa1.x, qa1.y, hi[2], lo[2]); split2(qa1.z, qa1.w, hi[3], lo[3]);
        sts128(sb + cdst,          hi[0], hi[1], hi[2], hi[3]);
        sts128(sb + G1_TSZ + cdst, lo[0], lo[1], lo[2], lo[3]);
        split2(ea0.x, ea0.y, hi[0], lo[0]); split2(ea0.z, ea0.w, hi[1], lo[1]);
        split2(ea1.x, ea1.y, hi[2], lo[2]); split2(ea1.z, ea1.w, hi[3], lo[3]);
        sts128(sb + 2 * G1_TSZ + cdst, hi[0], hi[1], hi[2], hi[3]);
        sts128(sb + 3 * G1_TSZ + cdst, lo[0], lo[1], lo[2], lo[3]);
        qa0 = *(const float4*)(gQ + 16);  qa1 = *(const float4*)(gQ + 20);
        ea0 = *(const float4*)(gE + 16);  ea1 = *(const float4*)(gE + 20);
    }
    __syncthreads();

    int lr = lane & 15;
    uint32_t koff = (lane >> 4) * 16;

    for (int kc = 0; kc < 64; kc++) {
        int s = kc & 1;

        // convert held regs (chunk kc+1) -> T[s^1]; then issue LDG for chunk kc+2
        if (kc + 1 < 64) {
            uint32_t tb1 = sb + (s ^ 1) * G1_STAGE;
            uint32_t hi[4], lo[4];
            split2(qa0.x, qa0.y, hi[0], lo[0]); split2(qa0.z, qa0.w, hi[1], lo[1]);
            split2(qa1.x, qa1.y, hi[2], lo[2]); split2(qa1.z, qa1.w, hi[3], lo[3]);
            sts128(tb1 + cdst,          hi[0], hi[1], hi[2], hi[3]);
            sts128(tb1 + G1_TSZ + cdst, lo[0], lo[1], lo[2], lo[3]);
            split2(ea0.x, ea0.y, hi[0], lo[0]); split2(ea0.z, ea0.w, hi[1], lo[1]);
            split2(ea1.x, ea1.y, hi[2], lo[2]); split2(ea1.z, ea1.w, hi[3], lo[3]);
            sts128(tb1 + 2 * G1_TSZ + cdst, hi[0], hi[1], hi[2], hi[3]);
            sts128(tb1 + 3 * G1_TSZ + cdst, lo[0], lo[1], lo[2], lo[3]);
        }
        if (kc + 2 < 64) {
            const float* q = gQ + (size_t)(kc + 2) * 16;
            const float* e = gE + (size_t)(kc + 2) * 16;
            qa0 = *(const float4*)(q);     qa1 = *(const float4*)(q + 4);
            ea0 = *(const float4*)(e);     ea1 = *(const float4*)(e + 4);
        }

        // ---- MMA on T[s] ----
        uint32_t tb = sb + s * G1_STAGE;
        uint32_t bh[2][4], bl[2][4];
        #pragma unroll
        for (int p = 0; p < 2; p++) {
            uint32_t a = tb + 2 * G1_TSZ + (wn * 32 + p * 16 + lr) * G1_TROW + koff;
            ldsm_x4(a, bh[p][0], bh[p][1], bh[p][2], bh[p][3]);
            ldsm_x4(a + G1_TSZ, bl[p][0], bl[p][1], bl[p][2], bl[p][3]);
        }
        #pragma unroll
        for (int mt = 0; mt < 4; mt++) {
            uint32_t ah[4], al[4];
            uint32_t a = tb + (wm * 64 + mt * 16 + lr) * G1_TROW + koff;
            ldsm_x4(a, ah[0], ah[1], ah[2], ah[3]);
            ldsm_x4(a + G1_TSZ, al[0], al[1], al[2], al[3]);
            #pragma unroll
            for (int p = 0; p < 2; p++)
                #pragma unroll
                for (int q = 0; q < 2; q++) {
                    int nt = p * 2 + q;
                    mma16816(c[mt][nt], ah, bh[p][q], bh[p][q + 2]);
                    mma16816(c[mt][nt], ah, bl[p][q], bl[p][q + 2]);
                    mma16816(c[mt][nt], al, bh[p][q], bh[p][q + 2]);
                }
        }
        __syncthreads();   // MMA(kc) done everywhere; T[s] reusable; T[s^1] tiles complete
    }

    int r0 = m0 + wm * 64 + (lane >> 2);
    int col = n0 + wn * 32 + (lane & 3) * 2;
    #pragma unroll
    for (int mt = 0; mt < 4; mt++)
        #pragma unroll
        for (int nt = 0; nt < 4; nt++) {
            size_t base = boff + (size_t)(r0 + mt * 16) * 1024 + col + nt * 8;
            *(float2*)(g_scores + base) = make_float2(c[mt][nt][0], c[mt][nt][1]);
            *(float2*)(g_scores + base + 8 * 1024) = make_float2(c[mt][nt][2], c[mt][nt][3]);
        }
}

// ============ softmax: fp32 rows of g_scores -> fp16 g_w ============

__global__ void __launch_bounds__(256)
softmax_kernel() {
    __shared__ float red[40];
    size_t row = blockIdx.x;
    const float4* p = (const float4*)(g_scores + (row << 10));
    int t = threadIdx.x, wid = t >> 5, lane = t & 31;

    float4 v = p[t];
    float m = fmaxf(fmaxf(v.x, v.y), fmaxf(v.z, v.w));
    #pragma unroll
    for (int o = 16; o; o >>= 1) m = fmaxf(m, __shfl_xor_sync(0xffffffffu, m, o));
    if (lane == 0) red[wid] = m;
    __syncthreads();
    if (t == 0) {
        float mm = red[0];
        #pragma unroll
        for (int i = 1; i < 8; i++) mm = fmaxf(mm, red[i]);
        red[8] = mm;
    }
    __syncthreads();
    float mx = red[8];

    float4 e = make_float4(__expf(v.x - mx), __expf(v.y - mx),
                           __expf(v.z - mx), __expf(v.w - mx));
    float s = e.x + e.y + e.z + e.w;
    #pragma unroll
    for (int o = 16; o; o >>= 1) s += __shfl_xor_sync(0xffffffffu, s, o);
    if (lane == 0) red[16 + wid] = s;
    __syncthreads();
    if (t == 0) {
        float ss = red[16];
        #pragma unroll
        for (int i = 1; i < 8; i++) ss += red[16 + i];
        red[24] = 1.0f / ss;
    }
    __syncthreads();
    float inv = red[24];

    __half2* w = (__half2*)(g_w + (row << 10));
    w[t * 2]     = __floats2half2_rn(e.x * inv, e.y * inv);
    w[t * 2 + 1] = __floats2half2_rn(e.z * inv, e.w * inv);
}

// ============ GEMM2: out = W @ V (pure fp16, k-chunk 64, 3-slot rotation) ============

__device__ __forceinline__ void g2_load(uint32_t base, int tid, int kc,
                                        const __half* gA, const __half* gB) {
    #pragma unroll
    for (int i = 0; i < 4; i++) {
        int id = i * 256 + tid;            // 0..1023
        int row = id >> 3, seg = id & 7;
        uint32_t off = row * G2_ROW + seg * 16;
        size_t go = (size_t)row * 1024 + kc * 64 + seg * 8;
        cp_async16(base + off, gA + go);
        cp_async16(base + G2_TILE + off, gB + go);
    }
    CP_COMMIT();
}

__global__ void __launch_bounds__(256, 2)
gemm2_kernel(float* __restrict__ O) {
    extern __shared__ char smem[];
    uint32_t sb = smem_u32(smem);
    int tid = threadIdx.x, wid = tid >> 5, lane = tid & 31;
    int wm = wid >> 2, wn = wid & 3;
    int b = blockIdx.z;
    int m0 = blockIdx.y << 7, n0 = blockIdx.x << 7;
    size_t boff = (size_t)b << 20;

    const __half* gA = g_w + boff + (size_t)m0 * 1024;
    const __half* gB = g_et + boff + (size_t)n0 * 1024;

    float c[4][4][4];
    #pragma unroll
    for (int i = 0; i < 4; i++)
        #pragma unroll
        for (int j = 0; j < 4; j++)
            #pragma unroll
            for (int k = 0; k < 4; k++) c[i][j][k] = 0.f;

    g2_load(sb + 0 * 2 * G2_TILE, tid, 0, gA, gB);
    g2_load(sb + 1 * 2 * G2_TILE, tid, 1, gA, gB);

    int lr = lane & 15;
    uint32_t lkoff = (lane >> 4) * 16;

    int slot = 0;
    for (int kc = 0; kc < 16; kc++) {
        if (kc < 15) { CP_WAIT(1); } else { CP_WAIT(0); }
        __syncthreads();

        uint32_t abase = sb + slot * 2 * G2_TILE;
        #pragma unroll
        for (int ks = 0; ks < 4; ks++) {
            uint32_t koff = ks * 32 + lkoff;
            uint32_t ah[4][4], bh[2][4];
            #pragma unroll
            for (int mt = 0; mt < 4; mt++) {
                uint32_t a = abase + (wm * 64 + mt * 16 + lr) * G2_ROW + koff;
                ldsm_x4(a, ah[mt][0], ah[mt][1], ah[mt][2], ah[mt][3]);
            }
            #pragma unroll
            for (int p = 0; p < 2; p++) {
                uint32_t a = abase + G2_TILE + (wn * 32 + p * 16 + lr) * G2_ROW + koff;
                ldsm_x4(a, bh[p][0], bh[p][1], bh[p][2], bh[p][3]);
            }
            #pragma unroll
            for (int mt = 0; mt < 4; mt++)
                #pragma unroll
                for (int p = 0; p < 2; p++)
                    #pragma unroll
                    for (int q = 0; q < 2; q++)
                        mma16816(c[mt][p * 2 + q], ah[mt], bh[p][q], bh[p][q + 2]);
        }

        if (kc + 2 < 16) {
            int ns = kc + 2 - ((kc + 2) / 3) * 3;  // (kc+2) % 3
            g2_load(sb + ns * 2 * G2_TILE, tid, kc + 2, gA, gB);
        }
        slot = (slot == 2) ? 0 : slot + 1;
    }

    int r0 = m0 + wm * 64 + (lane >> 2);
    int col = n0 + wn * 32 + (lane & 3) * 2;
    #pragma unroll
    for (int mt = 0; mt < 4; mt++)
        #pragma unroll
        for (int nt = 0; nt < 4; nt++) {
            size_t base = boff + (size_t)(r0 + mt * 16) * 1024 + col + nt * 8;
            *(float2*)(O + base) = make_float2(c[mt][nt][0], c[mt][nt][1]);
            *(float2*)(O + base + 8 * 1024) = make_float2(c[mt][nt][2], c[mt][nt][3]);
        }
}

// ============ launcher ============

extern "C" void kernel_launch(void* const* d_in, const int* in_sizes, int n_in,
                              void* d_out, int out_size) {
    const float* dec = (const float*)d_in[0];   // decoder_hidden  [16,1024,1024]
    const float* enc = (const float*)d_in[1];   // encoder_outputs [16,1024,1024]
    float* out = (float*)d_out;

    cudaFuncSetAttribute(gemm1_kernel, cudaFuncAttributeMaxDynamicSharedMemorySize, G1_SMEM);
    cudaFuncSetAttribute(gemm2_kernel, cudaFuncAttributeMaxDynamicSharedMemorySize, G2_SMEM);

    et_kernel<<<dim3(16, 16, 16), 256>>>(enc);
    gemm1_kernel<<<dim3(8, 8, 16), 256, G1_SMEM>>>(dec, enc);
    softmax_kernel<<<16384, 256>>>();
    gemm2_kernel<<<dim3(8, 8, 16), 256, G2_SMEM>>>(out);
}

// round 12
// speedup vs baseline: 1.0654x; 1.0654x over previous
#include <cuda_runtime.h>
#include <cuda_fp16.h>
#include <cstdint>

// ============ helpers ============

__device__ __forceinline__ uint32_t smem_u32(const void* p) {
    uint32_t a;
    asm("{ .reg .u64 t; cvta.to.shared.u64 t, %1; cvt.u32.u64 %0, t; }" : "=r"(a) : "l"(p));
    return a;
}

__device__ __forceinline__ void cp_async16(uint32_t saddr, const void* gaddr) {
    asm volatile("cp.async.cg.shared.global [%0], [%1], 16;" :: "r"(saddr), "l"(gaddr));
}
#define CP_COMMIT() asm volatile("cp.async.commit_group;" ::: "memory")
#define CP_WAIT(N)  asm volatile("cp.async.wait_group %0;" :: "n"(N) : "memory")

__device__ __forceinline__ void ldsm_x4(uint32_t addr, uint32_t& r0, uint32_t& r1,
                                        uint32_t& r2, uint32_t& r3) {
    asm volatile("ldmatrix.sync.aligned.m8n8.x4.shared.b16 {%0,%1,%2,%3}, [%4];"
                 : "=r"(r0), "=r"(r1), "=r"(r2), "=r"(r3) : "r"(addr));
}

__device__ __forceinline__ void lds128(uint32_t addr, uint32_t& x, uint32_t& y,
                                       uint32_t& z, uint32_t& w) {
    asm volatile("ld.shared.v4.b32 {%0,%1,%2,%3}, [%4];"
                 : "=r"(x), "=r"(y), "=r"(z), "=r"(w) : "r"(addr));
}
__device__ __forceinline__ void sts128(uint32_t a, uint32_t x, uint32_t y, uint32_t z, uint32_t w) {
    asm volatile("st.shared.v4.b32 [%0], {%1,%2,%3,%4};"
                 :: "r"(a), "r"(x), "r"(y), "r"(z), "r"(w) : "memory");
}

__device__ __forceinline__ void mma16816(float* c, const uint32_t* a, uint32_t b0, uint32_t b1) {
    asm volatile(
        "mma.sync.aligned.m16n8k16.row.col.f32.f16.f16.f32 "
        "{%0,%1,%2,%3}, {%4,%5,%6,%7}, {%8,%9}, {%0,%1,%2,%3};"
        : "+f"(c[0]), "+f"(c[1]), "+f"(c[2]), "+f"(c[3])
        : "r"(a[0]), "r"(a[1]), "r"(a[2]), "r"(a[3]), "r"(b0), "r"(b1));
}

__device__ __forceinline__ void split2(float v0, float v1, uint32_t& hi, uint32_t& lo) {
    __half h0 = __float2half_rn(v0), h1 = __float2half_rn(v1);
    __half2 hh = __halves2half2(h0, h1);
    hi = *(uint32_t*)&hh;
    __half2 ll = __floats2half2_rn(v0 - __half2float(h0), v1 - __half2float(h1));
    lo = *(uint32_t*)&ll;
}

// ============ device scratch ============

static constexpr size_t NEL = 16ull * 1024 * 1024;  // 16 x 1024 x 1024

__device__ __half g_w[NEL];     // softmax weights, fp16
__device__ __half g_et[NEL];    // E^T per batch, fp16: [b][d][k]
__device__ float  g_scores[NEL];

// gemm1 fp16 MMA tile: 128 rows x 32 halves, stride 80 B (conflict-free)
static constexpr int ROWB = 80;
static constexpr int TILEB = 128 * ROWB;  // 10240 B

// ---- GEMM1 smem layout (k32, single staging + single tiles; R5/R10-proven) ----
static constexpr int G1_ROW32 = 144;
static constexpr int G1_STG   = 128 * G1_ROW32;      // 18432 B per operand
static constexpr int G1_SA    = 0;
static constexpr int G1_SB    = G1_STG;
static constexpr int G1_TQH   = 2 * G1_STG;
static constexpr int G1_TQL   = G1_TQH + TILEB;
static constexpr int G1_TEH   = G1_TQH + 2 * TILEB;
static constexpr int G1_TEL   = G1_TQH + 3 * TILEB;
static constexpr int G1_SMEM  = G1_TQH + 4 * TILEB;  // 77824 B

// ---- GEMM2 smem layout (k64, 3-slot rotation; R10-proven) ----
static constexpr int G2_ROW  = 144;                  // 64 halves = 128B data + 16 pad
static constexpr int G2_TILE = 128 * G2_ROW;         // 18432 B per operand
static constexpr int G2_SMEM = 3 * 2 * G2_TILE;      // 110592 B

// ============ GEMM1: scores = Q @ E^T, convert-in-kernel, 3-term split ============
// Epilogue: each CTA also convert-transposes its (d0=m0, k0=n0) 128x128 E block -> g_et.

__device__ __forceinline__ void g1_cp(uint32_t sb, int tid, int kc,
                                      const float* gQ, const float* gE) {
    #pragma unroll
    for (int i = 0; i < 4; i++) {
        int id = i * 256 + tid;           // 0..1023
        int row = id >> 3, seg = id & 7;
        uint32_t off = row * G1_ROW32 + seg * 16;
        size_t go = (size_t)row * 1024 + kc * 32 + seg * 4;
        cp_async16(sb + G1_SA + off, gQ + go);
        cp_async16(sb + G1_SB + off, gE + go);
    }
    CP_COMMIT();
}

__global__ void __launch_bounds__(256, 2)
gemm1_kernel(const float* __restrict__ Q, const float* __restrict__ E) {
    extern __shared__ char smem[];
    uint32_t sb = smem_u32(smem);
    int tid = threadIdx.x, wid = tid >> 5, lane = tid & 31;
    int wm = wid >> 2, wn = wid & 3;
    int b = blockIdx.z;
    int m0 = blockIdx.y << 7, n0 = blockIdx.x << 7;
    size_t boff = (size_t)b << 20;

    const float* gQ = Q + boff + (size_t)m0 * 1024;
    const float* gE = E + boff + (size_t)n0 * 1024;

    float c[4][4][4];
    #pragma unroll
    for (int i = 0; i < 4; i++)
        #pragma unroll
        for (int j = 0; j < 4; j++)
            #pragma unroll
            for (int k = 0; k < 4; k++) c[i][j][k] = 0.f;

    g1_cp(sb, tid, 0, gQ, gE);

    int lr = lane & 15;
    uint32_t lkoff = (lane >> 4) * 16;  // bytes

    int cm = tid >> 1;
    int cko = (tid & 1) * 16;
    uint32_t csrc = cm * G1_ROW32 + cko * 4;
    uint32_t cdst = cm * 80 + cko * 2;

    for (int kc = 0; kc < 32; kc++) {
        CP_WAIT(0);
        __syncthreads();   // staging(kc) ready; MMA(kc-1) done -> tiles reusable

        // ---- convert staging -> fp16 hi/lo tiles ----
        {
            uint32_t ra[4][4], rb[4][4];
            #pragma unroll
            for (int j = 0; j < 4; j++)
                lds128(sb + G1_SA + csrc + j * 16, ra[j][0], ra[j][1], ra[j][2], ra[j][3]);
            #pragma unroll
            for (int j = 0; j < 4; j++)
                lds128(sb + G1_SB + csrc + j * 16, rb[j][0], rb[j][1], rb[j][2], rb[j][3]);

            uint32_t hi[8], lo[8];
            #pragma unroll
            for (int j = 0; j < 4; j++) {
                split2(__uint_as_float(ra[j][0]), __uint_as_float(ra[j][1]), hi[j * 2], lo[j * 2]);
                split2(__uint_as_float(ra[j][2]), __uint_as_float(ra[j][3]), hi[j * 2 + 1], lo[j * 2 + 1]);
            }
            sts128(sb + G1_TQH + cdst,      hi[0], hi[1], hi[2], hi[3]);
            sts128(sb + G1_TQH + cdst + 16, hi[4], hi[5], hi[6], hi[7]);
            sts128(sb + G1_TQL + cdst,      lo[0], lo[1], lo[2], lo[3]);
            sts128(sb + G1_TQL + cdst + 16, lo[4], lo[5], lo[6], lo[7]);
            #pragma unroll
            for (int j = 0; j < 4; j++) {
                split2(__uint_as_float(rb[j][0]), __uint_as_float(rb[j][1]), hi[j * 2], lo[j * 2]);
                split2(__uint_as_float(rb[j][2]), __uint_as_float(rb[j][3]), hi[j * 2 + 1], lo[j * 2 + 1]);
            }
            sts128(sb + G1_TEH + cdst,      hi[0], hi[1], hi[2], hi[3]);
            sts128(sb + G1_TEH + cdst + 16, hi[4], hi[5], hi[6], hi[7]);
            sts128(sb + G1_TEL + cdst,      lo[0], lo[1], lo[2], lo[3]);
            sts128(sb + G1_TEL + cdst + 16, lo[4], lo[5], lo[6], lo[7]);
        }
        __syncthreads();   // tiles ready; staging free for next cp

        if (kc + 1 < 32) g1_cp(sb, tid, kc + 1, gQ, gE);

        // ---- MMA phase ----
        #pragma unroll
        for (int ks = 0; ks < 2; ks++) {
            uint32_t koff = ks * 32 + lkoff;
            uint32_t bh[2][4], bl[2][4];
            #pragma unroll
            for (int p = 0; p < 2; p++) {
                uint32_t a = sb + G1_TEH + (wn * 32 + p * 16 + lr) * ROWB + koff;
                ldsm_x4(a, bh[p][0], bh[p][1], bh[p][2], bh[p][3]);
                ldsm_x4(a + TILEB, bl[p][0], bl[p][1], bl[p][2], bl[p][3]);
            }
            #pragma unroll
            for (int mt = 0; mt < 4; mt++) {
                uint32_t ah[4], al[4];
                uint32_t a = sb + G1_TQH + (wm * 64 + mt * 16 + lr) * ROWB + koff;
                ldsm_x4(a, ah[0], ah[1], ah[2], ah[3]);
                ldsm_x4(a + TILEB, al[0], al[1], al[2], al[3]);
                #pragma unroll
                for (int p = 0; p < 2; p++)
                    #pragma unroll
                    for (int q = 0; q < 2; q++) {
                        int nt = p * 2 + q;
                        mma16816(c[mt][nt], ah, bh[p][q], bh[p][q + 2]);
                        mma16816(c[mt][nt], ah, bl[p][q], bl[p][q + 2]);
                        mma16816(c[mt][nt], al, bh[p][q], bh[p][q + 2]);
                    }
            }
        }
    }

    // ---- write scores ----
    int r0 = m0 + wm * 64 + (lane >> 2);
    int col = n0 + wn * 32 + (lane & 3) * 2;
    #pragma unroll
    for (int mt = 0; mt < 4; mt++)
        #pragma unroll
        for (int nt = 0; nt < 4; nt++) {
            size_t base = boff + (size_t)(r0 + mt * 16) * 1024 + col + nt * 8;
            *(float2*)(g_scores + base) = make_float2(c[mt][nt][0], c[mt][nt][1]);
            *(float2*)(g_scores + base + 8 * 1024) = make_float2(c[mt][nt][2], c[mt][nt][3]);
        }

    // ---- fused E^T epilogue: convert-transpose E block (d0=m0, k0=n0) -> g_et ----
    __syncthreads();                 // last MMA's LDSM reads done; smem reusable
    {
        __half* ts = (__half*)smem;  // 64 x 65 halves scratch
        int f4id = tid & 15, rr = tid >> 4;
        int lane5 = tid >> 5;
        #pragma unroll
        for (int sub = 0; sub < 4; sub++) {
            int d0 = m0 + (sub >> 1) * 64, k0 = n0 + (sub & 1) * 64;
            #pragma unroll
            for (int pass = 0; pass < 4; pass++) {
                int k = pass * 16 + rr;
                float4 v = *(const float4*)(E + boff + (size_t)(k0 + k) * 1024 + d0 + f4id * 4);
                __half* rp = ts + k * 65 + f4id * 4;
                rp[0] = __float2half_rn(v.x);
                rp[1] = __float2half_rn(v.y);
                rp[2] = __float2half_rn(v.z);
                rp[3] = __float2half_rn(v.w);
            }
            __syncthreads();
            #pragma unroll
            for (int pass = 0; pass < 8; pass++) {
                int dd = pass * 8 + lane5;
                int kk = lane * 2;
                __half2 o = __halves2half2(ts[kk * 65 + dd], ts[(kk + 1) * 65 + dd]);
                *(__half2*)(g_et + boff + (size_t)(d0 + dd) * 1024 + k0 + kk) = o;
            }
            __syncthreads();
        }
    }
}

// ============ softmax: fp32 rows of g_scores -> fp16 g_w ============

__global__ void __launch_bounds__(256)
softmax_kernel() {
    __shared__ float red[40];
    size_t row = blockIdx.x;
    const float4* p = (const float4*)(g_scores + (row << 10));
    int t = threadIdx.x, wid = t >> 5, lane = t & 31;

    float4 v = p[t];
    float m = fmaxf(fmaxf(v.x, v.y), fmaxf(v.z, v.w));
    #pragma unroll
    for (int o = 16; o; o >>= 1) m = fmaxf(m, __shfl_xor_sync(0xffffffffu, m, o));
    if (lane == 0) red[wid] = m;
    __syncthreads();
    if (t == 0) {
        float mm = red[0];
        #pragma unroll
        for (int i = 1; i < 8; i++) mm = fmaxf(mm, red[i]);
        red[8] = mm;
    }
    __syncthreads();
    float mx = red[8];

    float4 e = make_float4(__expf(v.x - mx), __expf(v.y - mx),
                           __expf(v.z - mx), __expf(v.w - mx));
    float s = e.x + e.y + e.z + e.w;
    #pragma unroll
    for (int o = 16; o; o >>= 1) s += __shfl_xor_sync(0xffffffffu, s, o);
    if (lane == 0) red[16 + wid] = s;
    __syncthreads();
    if (t == 0) {
        float ss = red[16];
        #pragma unroll
        for (int i = 1; i < 8; i++) ss += red[16 + i];
        red[24] = 1.0f / ss;
    }
    __syncthreads();
    float inv = red[24];

    __half2* w = (__half2*)(g_w + (row << 10));
    w[t * 2]     = __floats2half2_rn(e.x * inv, e.y * inv);
    w[t * 2 + 1] = __floats2half2_rn(e.z * inv, e.w * inv);
}

// ============ GEMM2: out = W @ V (pure fp16, k-chunk 64, 3-slot rotation) ============

__device__ __forceinline__ void g2_load(uint32_t base, int tid, int kc,
                                        const __half* gA, const __half* gB) {
    #pragma unroll
    for (int i = 0; i < 4; i++) {
        int id = i * 256 + tid;            // 0..1023
        int row = id >> 3, seg = id & 7;
        uint32_t off = row * G2_ROW + seg * 16;
        size_t go = (size_t)row * 1024 + kc * 64 + seg * 8;
        cp_async16(base + off, gA + go);
        cp_async16(base + G2_TILE + off, gB + go);
    }
    CP_COMMIT();
}

__global__ void __launch_bounds__(256, 2)
gemm2_kernel(float* __restrict__ O) {
    extern __shared__ char smem[];
    uint32_t sb = smem_u32(smem);
    int tid = threadIdx.x, wid = tid >> 5, lane = tid & 31;
    int wm = wid >> 2, wn = wid & 3;
    int b = blockIdx.z;
    int m0 = blockIdx.y << 7, n0 = blockIdx.x << 7;
    size_t boff = (size_t)b << 20;

    const __half* gA = g_w + boff + (size_t)m0 * 1024;
    const __half* gB = g_et + boff + (size_t)n0 * 1024;

    float c[4][4][4];
    #pragma unroll
    for (int i = 0; i < 4; i++)
        #pragma unroll
        for (int j = 0; j < 4; j++)
            #pragma unroll
            for (int k = 0; k < 4; k++) c[i][j][k] = 0.f;

    g2_load(sb + 0 * 2 * G2_TILE, tid, 0, gA, gB);
    g2_load(sb + 1 * 2 * G2_TILE, tid, 1, gA, gB);

    int lr = lane & 15;
    uint32_t lkoff = (lane >> 4) * 16;

    int slot = 0;
    for (int kc = 0; kc < 16; kc++) {
        if (kc < 15) { CP_WAIT(1); } else { CP_WAIT(0); }
        __syncthreads();

        uint32_t abase = sb + slot * 2 * G2_TILE;
        #pragma unroll
        for (int ks = 0; ks < 4; ks++) {
            uint32_t koff = ks * 32 + lkoff;
            uint32_t ah[4][4], bh[2][4];
            #pragma unroll
            for (int mt = 0; mt < 4; mt++) {
                uint32_t a = abase + (wm * 64 + mt * 16 + lr) * G2_ROW + koff;
                ldsm_x4(a, ah[mt][0], ah[mt][1], ah[mt][2], ah[mt][3]);
            }
            #pragma unroll
            for (int p = 0; p < 2; p++) {
                uint32_t a = abase + G2_TILE + (wn * 32 + p * 16 + lr) * G2_ROW + koff;
                ldsm_x4(a, bh[p][0], bh[p][1], bh[p][2], bh[p][3]);
            }
            #pragma unroll
            for (int mt = 0; mt < 4; mt++)
                #pragma unroll
                for (int p = 0; p < 2; p++)
                    #pragma unroll
                    for (int q = 0; q < 2; q++)
                        mma16816(c[mt][p * 2 + q], ah[mt], bh[p][q], bh[p][q + 2]);
        }

        if (kc + 2 < 16) {
            int ns = kc + 2 - ((kc + 2) / 3) * 3;  // (kc+2) % 3
            g2_load(sb + ns * 2 * G2_TILE, tid, kc + 2, gA, gB);
        }
        slot = (slot == 2) ? 0 : slot + 1;
    }

    int r0 = m0 + wm * 64 + (lane >> 2);
    int col = n0 + wn * 32 + (lane & 3) * 2;
    #pragma unroll
    for (int mt = 0; mt < 4; mt++)
        #pragma unroll
        for (int nt = 0; nt < 4; nt++) {
            size_t base = boff + (size_t)(r0 + mt * 16) * 1024 + col + nt * 8;
            *(float2*)(O + base) = make_float2(c[mt][nt][0], c[mt][nt][1]);
            *(float2*)(O + base + 8 * 1024) = make_float2(c[mt][nt][2], c[mt][nt][3]);
        }
}

// ============ launcher ============

extern "C" void kernel_launch(void* const* d_in, const int* in_sizes, int n_in,
                              void* d_out, int out_size) {
    const float* dec = (const float*)d_in[0];   // decoder_hidden  [16,1024,1024]
    const float* enc = (const float*)d_in[1];   // encoder_outputs [16,1024,1024]
    float* out = (float*)d_out;

    cudaFuncSetAttribute(gemm1_kernel, cudaFuncAttributeMaxDynamicSharedMemorySize, G1_SMEM);
    cudaFuncSetAttribute(gemm2_kernel, cudaFuncAttributeMaxDynamicSharedMemorySize, G2_SMEM);

    gemm1_kernel<<<dim3(8, 8, 16), 256, G1_SMEM>>>(dec, enc);
    softmax_kernel<<<16384, 256>>>();
    gemm2_kernel<<<dim3(8, 8, 16), 256, G2_SMEM>>>(out);
}

// round 13
// speedup vs baseline: 1.0752x; 1.0092x over previous
#include <cuda_runtime.h>
#include <cuda_fp16.h>
#include <cstdint>

// ============ helpers ============

__device__ __forceinline__ uint32_t smem_u32(const void* p) {
    uint32_t a;
    asm("{ .reg .u64 t; cvta.to.shared.u64 t, %1; cvt.u32.u64 %0, t; }" : "=r"(a) : "l"(p));
    return a;
}

__device__ __forceinline__ void cp_async16(uint32_t saddr, const void* gaddr) {
    asm volatile("cp.async.cg.shared.global [%0], [%1], 16;" :: "r"(saddr), "l"(gaddr));
}
#define CP_COMMIT() asm volatile("cp.async.commit_group;" ::: "memory")
#define CP_WAIT(N)  asm volatile("cp.async.wait_group %0;" :: "n"(N) : "memory")

__device__ __forceinline__ void ldsm_x4(uint32_t addr, uint32_t& r0, uint32_t& r1,
                                        uint32_t& r2, uint32_t& r3) {
    asm volatile("ldmatrix.sync.aligned.m8n8.x4.shared.b16 {%0,%1,%2,%3}, [%4];"
                 : "=r"(r0), "=r"(r1), "=r"(r2), "=r"(r3) : "r"(addr));
}

__device__ __forceinline__ void lds128(uint32_t addr, uint32_t& x, uint32_t& y,
                                       uint32_t& z, uint32_t& w) {
    asm volatile("ld.shared.v4.b32 {%0,%1,%2,%3}, [%4];"
                 : "=r"(x), "=r"(y), "=r"(z), "=r"(w) : "r"(addr));
}
__device__ __forceinline__ void sts128(uint32_t a, uint32_t x, uint32_t y, uint32_t z, uint32_t w) {
    asm volatile("st.shared.v4.b32 [%0], {%1,%2,%3,%4};"
                 :: "r"(a), "r"(x), "r"(y), "r"(z), "r"(w) : "memory");
}

__device__ __forceinline__ void mma16816(float* c, const uint32_t* a, uint32_t b0, uint32_t b1) {
    asm volatile(
        "mma.sync.aligned.m16n8k16.row.col.f32.f16.f16.f32 "
        "{%0,%1,%2,%3}, {%4,%5,%6,%7}, {%8,%9}, {%0,%1,%2,%3};"
        : "+f"(c[0]), "+f"(c[1]), "+f"(c[2]), "+f"(c[3])
        : "r"(a[0]), "r"(a[1]), "r"(a[2]), "r"(a[3]), "r"(b0), "r"(b1));
}

__device__ __forceinline__ void split2(float v0, float v1, uint32_t& hi, uint32_t& lo) {
    __half h0 = __float2half_rn(v0), h1 = __float2half_rn(v1);
    __half2 hh = __halves2half2(h0, h1);
    hi = *(uint32_t*)&hh;
    __half2 ll = __floats2half2_rn(v0 - __half2float(h0), v1 - __half2float(h1));
    lo = *(uint32_t*)&ll;
}

// ============ device scratch ============

static constexpr size_t NEL = 16ull * 1024 * 1024;  // 16 x 1024 x 1024

__device__ __half g_w[NEL];     // softmax weights, fp16
__device__ __half g_et[NEL];    // E^T per batch, fp16: [b][d][k]
__device__ float  g_scores[NEL];

// gemm1 fp16 MMA tile: 128 rows x 32 halves, stride 80 B (conflict-free)
static constexpr int ROWB = 80;
static constexpr int TILEB = 128 * ROWB;  // 10240 B

// ---- GEMM1 smem layout (k32, single staging + single tiles; R5/R10-proven) ----
static constexpr int G1_ROW32 = 144;
static constexpr int G1_STG   = 128 * G1_ROW32;      // 18432 B per operand
static constexpr int G1_SA    = 0;
static constexpr int G1_SB    = G1_STG;
static constexpr int G1_TQH   = 2 * G1_STG;
static constexpr int G1_TQL   = G1_TQH + TILEB;
static constexpr int G1_TEH   = G1_TQH + 2 * TILEB;
static constexpr int G1_TEL   = G1_TQH + 3 * TILEB;
static constexpr int G1_SMEM  = G1_TQH + 4 * TILEB;  // 77824 B

// ---- GEMM2 smem layout (k64, 3-slot rotation; R10-proven) ----
static constexpr int G2_ROW  = 144;                  // 64 halves = 128B data + 16 pad
static constexpr int G2_TILE = 128 * G2_ROW;         // 18432 B per operand
static constexpr int G2_SMEM = 3 * 2 * G2_TILE;      // 110592 B

// ============ GEMM1: scores = Q @ E^T, convert-in-kernel, 3-term split ============
// Epilogue: each CTA also convert-transposes its (d0=m0, k0=n0) 128x128 E block -> g_et.

__device__ __forceinline__ void g1_cp(uint32_t sb, int tid, int kc,
                                      const float* gQ, const float* gE) {
    #pragma unroll
    for (int i = 0; i < 4; i++) {
        int id = i * 256 + tid;           // 0..1023
        int row = id >> 3, seg = id & 7;
        uint32_t off = row * G1_ROW32 + seg * 16;
        size_t go = (size_t)row * 1024 + kc * 32 + seg * 4;
        cp_async16(sb + G1_SA + off, gQ + go);
        cp_async16(sb + G1_SB + off, gE + go);
    }
    CP_COMMIT();
}

__global__ void __launch_bounds__(256, 2)
gemm1_kernel(const float* __restrict__ Q, const float* __restrict__ E) {
    extern __shared__ char smem[];
    uint32_t sb = smem_u32(smem);
    int tid = threadIdx.x, wid = tid >> 5, lane = tid & 31;
    int wm = wid >> 2, wn = wid & 3;
    int b = blockIdx.z;
    int m0 = blockIdx.y << 7, n0 = blockIdx.x << 7;
    size_t boff = (size_t)b << 20;

    const float* gQ = Q + boff + (size_t)m0 * 1024;
    const float* gE = E + boff + (size_t)n0 * 1024;

    float c[4][4][4];
    #pragma unroll
    for (int i = 0; i < 4; i++)
        #pragma unroll
        for (int j = 0; j < 4; j++)
            #pragma unroll
            for (int k = 0; k < 4; k++) c[i][j][k] = 0.f;

    g1_cp(sb, tid, 0, gQ, gE);

    int lr = lane & 15;
    uint32_t lkoff = (lane >> 4) * 16;  // bytes

    int cm = tid >> 1;
    int cko = (tid & 1) * 16;
    uint32_t csrc = cm * G1_ROW32 + cko * 4;
    uint32_t cdst = cm * 80 + cko * 2;

    for (int kc = 0; kc < 32; kc++) {
        CP_WAIT(0);
        __syncthreads();   // staging(kc) ready; MMA(kc-1) done -> tiles reusable

        // ---- convert staging -> fp16 hi/lo tiles ----
        {
            uint32_t ra[4][4], rb[4][4];
            #pragma unroll
            for (int j = 0; j < 4; j++)
                lds128(sb + G1_SA + csrc + j * 16, ra[j][0], ra[j][1], ra[j][2], ra[j][3]);
            #pragma unroll
            for (int j = 0; j < 4; j++)
                lds128(sb + G1_SB + csrc + j * 16, rb[j][0], rb[j][1], rb[j][2], rb[j][3]);

            uint32_t hi[8], lo[8];
            #pragma unroll
            for (int j = 0; j < 4; j++) {
                split2(__uint_as_float(ra[j][0]), __uint_as_float(ra[j][1]), hi[j * 2], lo[j * 2]);
                split2(__uint_as_float(ra[j][2]), __uint_as_float(ra[j][3]), hi[j * 2 + 1], lo[j * 2 + 1]);
            }
            sts128(sb + G1_TQH + cdst,      hi[0], hi[1], hi[2], hi[3]);
            sts128(sb + G1_TQH + cdst + 16, hi[4], hi[5], hi[6], hi[7]);
            sts128(sb + G1_TQL + cdst,      lo[0], lo[1], lo[2], lo[3]);
            sts128(sb + G1_TQL + cdst + 16, lo[4], lo[5], lo[6], lo[7]);
            #pragma unroll
            for (int j = 0; j < 4; j++) {
                split2(__uint_as_float(rb[j][0]), __uint_as_float(rb[j][1]), hi[j * 2], lo[j * 2]);
                split2(__uint_as_float(rb[j][2]), __uint_as_float(rb[j][3]), hi[j * 2 + 1], lo[j * 2 + 1]);
            }
            sts128(sb + G1_TEH + cdst,      hi[0], hi[1], hi[2], hi[3]);
            sts128(sb + G1_TEH + cdst + 16, hi[4], hi[5], hi[6], hi[7]);
            sts128(sb + G1_TEL + cdst,      lo[0], lo[1], lo[2], lo[3]);
            sts128(sb + G1_TEL + cdst + 16, lo[4], lo[5], lo[6], lo[7]);
        }
        __syncthreads();   // tiles ready; staging free for next cp

        if (kc + 1 < 32) g1_cp(sb, tid, kc + 1, gQ, gE);

        // ---- MMA phase ----
        #pragma unroll
        for (int ks = 0; ks < 2; ks++) {
            uint32_t koff = ks * 32 + lkoff;
            uint32_t bh[2][4], bl[2][4];
            #pragma unroll
            for (int p = 0; p < 2; p++) {
                uint32_t a = sb + G1_TEH + (wn * 32 + p * 16 + lr) * ROWB + koff;
                ldsm_x4(a, bh[p][0], bh[p][1], bh[p][2], bh[p][3]);
                ldsm_x4(a + TILEB, bl[p][0], bl[p][1], bl[p][2], bl[p][3]);
            }
            #pragma unroll
            for (int mt = 0; mt < 4; mt++) {
                uint32_t ah[4], al[4];
                uint32_t a = sb + G1_TQH + (wm * 64 + mt * 16 + lr) * ROWB + koff;
                ldsm_x4(a, ah[0], ah[1], ah[2], ah[3]);
                ldsm_x4(a + TILEB, al[0], al[1], al[2], al[3]);
                #pragma unroll
                for (int p = 0; p < 2; p++)
                    #pragma unroll
                    for (int q = 0; q < 2; q++) {
                        int nt = p * 2 + q;
                        mma16816(c[mt][nt], ah, bh[p][q], bh[p][q + 2]);
                        mma16816(c[mt][nt], ah, bl[p][q], bl[p][q + 2]);
                        mma16816(c[mt][nt], al, bh[p][q], bh[p][q + 2]);
                    }
            }
        }
    }

    // ---- write scores ----
    int r0 = m0 + wm * 64 + (lane >> 2);
    int col = n0 + wn * 32 + (lane & 3) * 2;
    #pragma unroll
    for (int mt = 0; mt < 4; mt++)
        #pragma unroll
        for (int nt = 0; nt < 4; nt++) {
            size_t base = boff + (size_t)(r0 + mt * 16) * 1024 + col + nt * 8;
            *(float2*)(g_scores + base) = make_float2(c[mt][nt][0], c[mt][nt][1]);
            *(float2*)(g_scores + base + 8 * 1024) = make_float2(c[mt][nt][2], c[mt][nt][3]);
        }

    // ---- fused E^T epilogue: convert-transpose E block (d0=m0, k0=n0) -> g_et ----
    __syncthreads();                 // last MMA's LDSM reads done; smem reusable
    {
        __half* ts = (__half*)smem;  // 64 x 65 halves scratch
        int f4id = tid & 15, rr = tid >> 4;
        int lane5 = tid >> 5;
        #pragma unroll
        for (int sub = 0; sub < 4; sub++) {
            int d0 = m0 + (sub >> 1) * 64, k0 = n0 + (sub & 1) * 64;
            #pragma unroll
            for (int pass = 0; pass < 4; pass++) {
                int k = pass * 16 + rr;
                float4 v = *(const float4*)(E + boff + (size_t)(k0 + k) * 1024 + d0 + f4id * 4);
                __half* rp = ts + k * 65 + f4id * 4;
                rp[0] = __float2half_rn(v.x);
                rp[1] = __float2half_rn(v.y);
                rp[2] = __float2half_rn(v.z);
                rp[3] = __float2half_rn(v.w);
            }
            __syncthreads();
            #pragma unroll
            for (int pass = 0; pass < 8; pass++) {
                int dd = pass * 8 + lane5;
                int kk = lane * 2;
                __half2 o = __halves2half2(ts[kk * 65 + dd], ts[(kk + 1) * 65 + dd]);
                *(__half2*)(g_et + boff + (size_t)(d0 + dd) * 1024 + k0 + kk) = o;
            }
            __syncthreads();
        }
    }
}

// ============ softmax: warp-per-row, barrier-free ============
// 8 warps/block, 2048 blocks; each warp owns one row of 1024 fp32 scores.

__global__ void __launch_bounds__(256)
softmax_kernel() {
    int warp = threadIdx.x >> 5, lane = threadIdx.x & 31;
    size_t row = (size_t)blockIdx.x * 8 + warp;
    const float4* p = (const float4*)(g_scores + (row << 10));

    float4 v[8];
    #pragma unroll
    for (int i = 0; i < 8; i++) v[i] = p[i * 32 + lane];

    float m = -1e30f;
    #pragma unroll
    for (int i = 0; i < 8; i++)
        m = fmaxf(m, fmaxf(fmaxf(v[i].x, v[i].y), fmaxf(v[i].z, v[i].w)));
    #pragma unroll
    for (int o = 16; o; o >>= 1) m = fmaxf(m, __shfl_xor_sync(0xffffffffu, m, o));

    float s = 0.f;
    #pragma unroll
    for (int i = 0; i < 8; i++) {
        v[i].x = __expf(v[i].x - m); v[i].y = __expf(v[i].y - m);
        v[i].z = __expf(v[i].z - m); v[i].w = __expf(v[i].w - m);
        s += (v[i].x + v[i].y) + (v[i].z + v[i].w);
    }
    #pragma unroll
    for (int o = 16; o; o >>= 1) s += __shfl_xor_sync(0xffffffffu, s, o);
    float inv = 1.0f / s;

    __half2* w = (__half2*)(g_w + (row << 10));
    #pragma unroll
    for (int i = 0; i < 8; i++) {
        int e4 = i * 32 + lane;                     // float4 index
        w[e4 * 2]     = __floats2half2_rn(v[i].x * inv, v[i].y * inv);
        w[e4 * 2 + 1] = __floats2half2_rn(v[i].z * inv, v[i].w * inv);
    }
}

// ============ GEMM2: out = W @ V (fp16, k64, 3-slot; prefetch before MMA) ============

__device__ __forceinline__ void g2_load(uint32_t base, int tid, int kc,
                                        const __half* gA, const __half* gB) {
    #pragma unroll
    for (int i = 0; i < 4; i++) {
        int id = i * 256 + tid;            // 0..1023
        int row = id >> 3, seg = id & 7;
        uint32_t off = row * G2_ROW + seg * 16;
        size_t go = (size_t)row * 1024 + kc * 64 + seg * 8;
        cp_async16(base + off, gA + go);
        cp_async16(base + G2_TILE + off, gB + go);
    }
    CP_COMMIT();
}

__global__ void __launch_bounds__(256, 2)
gemm2_kernel(float* __restrict__ O) {
    extern __shared__ char smem[];
    uint32_t sb = smem_u32(smem);
    int tid = threadIdx.x, wid = tid >> 5, lane = tid & 31;
    int wm = wid >> 2, wn = wid & 3;
    int b = blockIdx.z;
    int m0 = blockIdx.y << 7, n0 = blockIdx.x << 7;
    size_t boff = (size_t)b << 20;

    const __half* gA = g_w + boff + (size_t)m0 * 1024;
    const __half* gB = g_et + boff + (size_t)n0 * 1024;

    float c[4][4][4];
    #pragma unroll
    for (int i = 0; i < 4; i++)
        #pragma unroll
        for (int j = 0; j < 4; j++)
            #pragma unroll
            for (int k = 0; k < 4; k++) c[i][j][k] = 0.f;

    g2_load(sb + 0 * 2 * G2_TILE, tid, 0, gA, gB);
    g2_load(sb + 1 * 2 * G2_TILE, tid, 1, gA, gB);

    int lr = lane & 15;
    uint32_t lkoff = (lane >> 4) * 16;

    int slot = 0;
    for (int kc = 0; kc < 16; kc++) {
        if (kc < 15) { CP_WAIT(1); } else { CP_WAIT(0); }
        __syncthreads();

        // prefetch FIRST: slot (kc+2)%3 untouched by MMA(kc); its readers fenced above
        if (kc + 2 < 16) {
            int ns = kc + 2 - ((kc + 2) / 3) * 3;  // (kc+2) % 3
            g2_load(sb + ns * 2 * G2_TILE, tid, kc + 2, gA, gB);
        }

        uint32_t abase = sb + slot * 2 * G2_TILE;
        #pragma unroll
        for (int ks = 0; ks < 4; ks++) {
            uint32_t koff = ks * 32 + lkoff;
            uint32_t ah[4][4], bh[2][4];
            #pragma unroll
            for (int mt = 0; mt < 4; mt++) {
                uint32_t a = abase + (wm * 64 + mt * 16 + lr) * G2_ROW + koff;
                ldsm_x4(a, ah[mt][0], ah[mt][1], ah[mt][2], ah[mt][3]);
            }
            #pragma unroll
            for (int p = 0; p < 2; p++) {
                uint32_t a = abase + G2_TILE + (wn * 32 + p * 16 + lr) * G2_ROW + koff;
                ldsm_x4(a, bh[p][0], bh[p][1], bh[p][2], bh[p][3]);
            }
            #pragma unroll
            for (int mt = 0; mt < 4; mt++)
                #pragma unroll
                for (int p = 0; p < 2; p++)
                    #pragma unroll
                    for (int q = 0; q < 2; q++)
                        mma16816(c[mt][p * 2 + q], ah[mt], bh[p][q], bh[p][q + 2]);
        }

        slot = (slot == 2) ? 0 : slot + 1;
    }

    int r0 = m0 + wm * 64 + (lane >> 2);
    int col = n0 + wn * 32 + (lane & 3) * 2;
    #pragma unroll
    for (int mt = 0; mt < 4; mt++)
        #pragma unroll
        for (int nt = 0; nt < 4; nt++) {
            size_t base = boff + (size_t)(r0 + mt * 16) * 1024 + col + nt * 8;
            *(float2*)(O + base) = make_float2(c[mt][nt][0], c[mt][nt][1]);
            *(float2*)(O + base + 8 * 1024) = make_float2(c[mt][nt][2], c[mt][nt][3]);
        }
}

// ============ launcher ============

extern "C" void kernel_launch(void* const* d_in, const int* in_sizes, int n_in,
                              void* d_out, int out_size) {
    const float* dec = (const float*)d_in[0];   // decoder_hidden  [16,1024,1024]
    const float* enc = (const float*)d_in[1];   // encoder_outputs [16,1024,1024]
    float* out = (float*)d_out;

    cudaFuncSetAttribute(gemm1_kernel, cudaFuncAttributeMaxDynamicSharedMemorySize, G1_SMEM);
    cudaFuncSetAttribute(gemm2_kernel, cudaFuncAttributeMaxDynamicSharedMemorySize, G2_SMEM);

    gemm1_kernel<<<dim3(8, 8, 16), 256, G1_SMEM>>>(dec, enc);
    softmax_kernel<<<2048, 256>>>();
    gemm2_kernel<<<dim3(8, 8, 16), 256, G2_SMEM>>>(out);
}